// round 12
// baseline (speedup 1.0000x reference)
#include <cuda_runtime.h>
#include <cuda_bf16.h>
#include <cuda_fp16.h>
#include <cstdint>
#include <cstddef>

// ---------------- problem constants ----------------
#define NMAX 50000
#define EMAX 800000
#define ETMAX (EMAX + NMAX)

// ---------------- device scratch ----------------
__device__ int   g_is64;
__device__ int   g_src[ETMAX];
__device__ int   g_dst[ETMAX];
__device__ int   g_cnt[NMAX];
__device__ int   g_rowptr[NMAX + 1];
__device__ int   g_cursor[NMAX];
__device__ int   g_part[64];
__device__ int   g_esrc[ETMAX];
__device__ __half g_h[(size_t)NMAX * 256];   // GEMM output, fp16 (agg gather only)
__device__ float g_as[(size_t)NMAX * 4];     // per-node src scores [N,H]
__device__ float g_ad[(size_t)NMAX * 4];     // per-node dst scores [N,H]
__device__ __nv_bfloat16 g_ahi[(size_t)NMAX * 256];  // A split hi (next GEMM input)
__device__ __nv_bfloat16 g_alo[(size_t)NMAX * 256];  // A split lo
__device__ __nv_bfloat16 g_bhi[256 * 256];           // W^T split hi [N,K]
__device__ __nv_bfloat16 g_blo[256 * 256];           // W^T split lo [N,K]

// =============================== CSR construction ==================================
__global__ void detect_kernel(const unsigned int* __restrict__ p, int E) {
    __shared__ int sor;
    if (threadIdx.x == 0) sor = 0;
    __syncthreads();
    int ns = E < 2048 ? E : 2048;
    unsigned int acc = 0;
    for (int i = threadIdx.x; i < ns; i += blockDim.x) acc |= p[2 * i + 1];
    if (acc) atomicOr(&sor, 1);
    __syncthreads();
    if (threadIdx.x == 0) g_is64 = (sor == 0) ? 1 : 0;
}
__global__ void zero_cnt_kernel(int n) {
    int i = blockIdx.x * blockDim.x + threadIdx.x;
    if (i < n) g_cnt[i] = 0;
}
__global__ void decode_count_kernel(const void* __restrict__ eptr, int E, int n) {
    int i = blockIdx.x * blockDim.x + threadIdx.x;
    int ET = E + n;
    if (i >= ET) return;
    int s, d;
    if (i >= E) {
        s = d = i - E;
    } else if (g_is64) {
        const long long* p = (const long long*)eptr;
        s = (int)p[i];
        d = (int)p[(size_t)E + i];
    } else {
        const int* p = (const int*)eptr;
        s = p[i];
        d = p[E + i];
    }
    g_src[i] = s;
    g_dst[i] = d;
    atomicAdd(&g_cnt[d], 1);
}
__global__ void scan1_kernel(int n) {
    __shared__ int sh[1024];
    int i = blockIdx.x * 1024 + threadIdx.x;
    int v = (i < n) ? g_cnt[i] : 0;
    sh[threadIdx.x] = v;
    __syncthreads();
    for (int o = 1; o < 1024; o <<= 1) {
        int t = (threadIdx.x >= o) ? sh[threadIdx.x - o] : 0;
        __syncthreads();
        sh[threadIdx.x] += t;
        __syncthreads();
    }
    if (i < n) g_rowptr[i + 1] = sh[threadIdx.x];
    if (threadIdx.x == 1023) g_part[blockIdx.x] = sh[1023];
}
__global__ void scan2_kernel(int nb) {
    int acc = 0;
    for (int i = 0; i < nb; i++) {
        int t = g_part[i];
        g_part[i] = acc;
        acc += t;
    }
}
__global__ void scan3_kernel(int n) {
    int i = blockIdx.x * blockDim.x + threadIdx.x;
    if (i < n) g_rowptr[i + 1] += g_part[i >> 10];
    if (i == 0) g_rowptr[0] = 0;
}
__global__ void cursor_kernel(int n) {
    int i = blockIdx.x * blockDim.x + threadIdx.x;
    if (i < n) g_cursor[i] = g_rowptr[i];
}
__global__ void scatter_kernel(int ET) {
    int i = blockIdx.x * blockDim.x + threadIdx.x;
    if (i >= ET) return;
    int d = g_dst[i];
    int pos = atomicAdd(&g_cursor[d], 1);
    g_esrc[pos] = g_src[i];
}

// ============================ split conversions ==================================
__global__ void asplit_kernel(const float* __restrict__ src, int count4) {
    int i = blockIdx.x * blockDim.x + threadIdx.x;
    if (i >= count4) return;
    float4 v = ((const float4*)src)[i];
    __nv_bfloat16 h0 = __float2bfloat16(v.x), h1 = __float2bfloat16(v.y);
    __nv_bfloat16 h2 = __float2bfloat16(v.z), h3 = __float2bfloat16(v.w);
    __nv_bfloat16 l0 = __float2bfloat16(v.x - __bfloat162float(h0));
    __nv_bfloat16 l1 = __float2bfloat16(v.y - __bfloat162float(h1));
    __nv_bfloat16 l2 = __float2bfloat16(v.z - __bfloat162float(h2));
    __nv_bfloat16 l3 = __float2bfloat16(v.w - __bfloat162float(h3));
    __nv_bfloat162* hp = (__nv_bfloat162*)g_ahi;
    __nv_bfloat162* lp = (__nv_bfloat162*)g_alo;
    hp[2 * i] = __nv_bfloat162(h0, h1);
    hp[2 * i + 1] = __nv_bfloat162(h2, h3);
    lp[2 * i] = __nv_bfloat162(l0, l1);
    lp[2 * i + 1] = __nv_bfloat162(l2, l3);
}
// W [K=256, N] fp32 -> W^T [N, 256] (hi, lo) bf16
__global__ void wsplit_kernel(const float* __restrict__ W, int N, int total) {
    int t = blockIdx.x * blockDim.x + threadIdx.x;
    if (t >= total) return;
    int k = t & 255, n = t >> 8;
    float v = W[(size_t)k * N + n];
    __nv_bfloat16 h = __float2bfloat16(v);
    g_bhi[n * 256 + k] = h;
    g_blo[n * 256 + k] = __float2bfloat16(v - __bfloat162float(h));
}
// zero the score accumulators (GEMM epilogue atomically accumulates into them)
__global__ void zero_scores_kernel(int cnt) {
    int i = blockIdx.x * blockDim.x + threadIdx.x;
    if (i < cnt) {
        g_as[i] = 0.f;
        g_ad[i] = 0.f;
    }
}

// ========== HMMA split-3 bf16 GEMM: 3-stage cp.async + ldmatrix fragments ==========
// h[M, ldC] cols [n0, n0+64) = A[M,256] @ W[256, ldC], stored fp16 (agg-only consumer).
// Block 128x64, 8 warps (4x2), warp tile 32x32, BK=32. D = AhBh + AhBl + AlBh (fp32).
// Epilogue fuses attention-score partials (from fp32 acc) into g_as/g_ad via atomics.
#define MMA_BF16(d, a, b)                                                              \
    asm volatile(                                                                       \
        "mma.sync.aligned.m16n8k16.row.col.f32.bf16.bf16.f32 "                          \
        "{%0,%1,%2,%3}, {%4,%5,%6,%7}, {%8,%9}, {%0,%1,%2,%3};"                         \
        : "+f"((d)[0]), "+f"((d)[1]), "+f"((d)[2]), "+f"((d)[3])                        \
        : "r"((a)[0]), "r"((a)[1]), "r"((a)[2]), "r"((a)[3]), "r"((b)[0]), "r"((b)[1]))

#define LDSM_X4(r, addr)                                                               \
    asm volatile("ldmatrix.sync.aligned.m8n8.x4.shared.b16 {%0,%1,%2,%3}, [%4];"       \
                 : "=r"((r)[0]), "=r"((r)[1]), "=r"((r)[2]), "=r"((r)[3])              \
                 : "r"(addr))

__device__ __forceinline__ void cp16(uint32_t dst, const void* src, int sz) {
    asm volatile("cp.async.cg.shared.global [%0], [%1], 16, %2;" :: "r"(dst), "l"(src),
                 "r"(sz) : "memory");
}

// stage layout (bytes): Ah 0 (10240), Al 10240, Bh 20480 (5120), Bl 25600; stage=30720
#define STG_B 30720
#define NSTG 3

__global__ __launch_bounds__(256) void hmma_gemm_kernel(__half* __restrict__ C, int M, int ldC,
                                                        const float* __restrict__ a_s,
                                                        const float* __restrict__ a_d,
                                                        int Cc, int H) {
    extern __shared__ char sm[];
    int tid = threadIdx.x, wid = tid >> 5, lane = tid & 31;
    int warp_m = wid & 3, warp_n = wid >> 2;
    int g = lane >> 2, t = lane & 3;
    int m0 = blockIdx.x * 128, n0 = blockIdx.y * 64;
    uint32_t sbase = (uint32_t)__cvta_generic_to_shared(sm);

    float acc[2][4][4];
#pragma unroll
    for (int mt = 0; mt < 2; mt++)
#pragma unroll
        for (int nt = 0; nt < 4; nt++)
#pragma unroll
            for (int r = 0; r < 4; r++) acc[mt][nt][r] = 0.f;

    int arow0 = tid >> 2, aq = tid & 3;
    int brow = tid >> 2, bq = tid & 3;

    auto load_chunk = [&](int c, int stg) {
        int kc = c * 32;
        uint32_t base = sbase + stg * STG_B;
#pragma unroll
        for (int half = 0; half < 2; half++) {
            int row = arow0 + half * 64;
            int gr = m0 + row;
            int sz = (gr < M) ? 16 : 0;
            int grc = (gr < M) ? gr : 0;
            size_t go = (size_t)grc * 256 + kc + aq * 8;
            uint32_t so = base + (uint32_t)(row * 40 + aq * 8) * 2;
            cp16(so, g_ahi + go, sz);
            cp16(so + 10240, g_alo + go, sz);
        }
        {
            size_t go = (size_t)(n0 + brow) * 256 + kc + bq * 8;
            uint32_t so = base + 20480 + (uint32_t)(brow * 40 + bq * 8) * 2;
            cp16(so, g_bhi + go, 16);
            cp16(so + 5120, g_blo + go, 16);
        }
        asm volatile("cp.async.commit_group;" ::: "memory");
    };

    uint32_t aoff[2];
#pragma unroll
    for (int mt = 0; mt < 2; mt++) {
        int row = warp_m * 32 + mt * 16 + (lane & 15);
        aoff[mt] = (uint32_t)(row * 40 + ((lane >> 4) & 1) * 8) * 2;
    }
    uint32_t boff[2];
#pragma unroll
    for (int ntp = 0; ntp < 2; ntp++) {
        int row = warp_n * 32 + ntp * 16 + ((lane >> 4) & 1) * 8 + (lane & 7);
        boff[ntp] = 20480u + (uint32_t)(row * 40 + ((lane >> 3) & 1) * 8) * 2;
    }

    load_chunk(0, 0);
    load_chunk(1, 1);

    for (int c = 0; c < 8; c++) {
        int stg = c % NSTG;
        if (c < 7)
            asm volatile("cp.async.wait_group 1;" ::: "memory");
        else
            asm volatile("cp.async.wait_group 0;" ::: "memory");
        __syncthreads();
        if (c + 2 < 8) load_chunk(c + 2, (c + 2) % NSTG);

        uint32_t stbase = sbase + stg * STG_B;
#pragma unroll
        for (int kk = 0; kk < 32; kk += 16) {
            uint32_t ah[2][4], al[2][4], bh[4][2], bl[4][2];
#pragma unroll
            for (int mt = 0; mt < 2; mt++) {
                uint32_t ad = stbase + aoff[mt] + kk * 2;
                LDSM_X4(ah[mt], ad);
                LDSM_X4(al[mt], ad + 10240);
            }
#pragma unroll
            for (int ntp = 0; ntp < 2; ntp++) {
                uint32_t bd = stbase + boff[ntp] + kk * 2;
                uint32_t rh[4], rl[4];
                LDSM_X4(rh, bd);
                LDSM_X4(rl, bd + 5120);
                bh[2 * ntp][0] = rh[0];
                bh[2 * ntp][1] = rh[1];
                bh[2 * ntp + 1][0] = rh[2];
                bh[2 * ntp + 1][1] = rh[3];
                bl[2 * ntp][0] = rl[0];
                bl[2 * ntp][1] = rl[1];
                bl[2 * ntp + 1][0] = rl[2];
                bl[2 * ntp + 1][1] = rl[3];
            }
#pragma unroll
            for (int mt = 0; mt < 2; mt++)
#pragma unroll
                for (int nt = 0; nt < 4; nt++) {
                    MMA_BF16(acc[mt][nt], ah[mt], bh[nt]);
                    MMA_BF16(acc[mt][nt], ah[mt], bl[nt]);
                    MMA_BF16(acc[mt][nt], al[mt], bh[nt]);
                }
        }
    }

    // epilogue: store h (fp16) + fused score partials (fp32 acc)
    int head = n0 / Cc;
#pragma unroll
    for (int mt = 0; mt < 2; mt++) {
        int r0 = m0 + warp_m * 32 + mt * 16 + g;
        float ss0 = 0.f, sd0 = 0.f, ss8 = 0.f, sd8 = 0.f;
#pragma unroll
        for (int nt = 0; nt < 4; nt++) {
            int col = n0 + warp_n * 32 + nt * 8 + t * 2;
            if (r0 < M)
                *(__half2*)(C + (size_t)r0 * ldC + col) =
                    __floats2half2_rn(acc[mt][nt][0], acc[mt][nt][1]);
            if (r0 + 8 < M)
                *(__half2*)(C + (size_t)(r0 + 8) * ldC + col) =
                    __floats2half2_rn(acc[mt][nt][2], acc[mt][nt][3]);
            float a0 = a_s[col], a1 = a_s[col + 1];
            float d0 = a_d[col], d1 = a_d[col + 1];
            ss0 += acc[mt][nt][0] * a0 + acc[mt][nt][1] * a1;
            sd0 += acc[mt][nt][0] * d0 + acc[mt][nt][1] * d1;
            ss8 += acc[mt][nt][2] * a0 + acc[mt][nt][3] * a1;
            sd8 += acc[mt][nt][2] * d0 + acc[mt][nt][3] * d1;
        }
#pragma unroll
        for (int o = 1; o < 4; o <<= 1) {
            ss0 += __shfl_xor_sync(0xffffffffu, ss0, o);
            sd0 += __shfl_xor_sync(0xffffffffu, sd0, o);
            ss8 += __shfl_xor_sync(0xffffffffu, ss8, o);
            sd8 += __shfl_xor_sync(0xffffffffu, sd8, o);
        }
        if (t == 0) {
            if (r0 < M) {
                atomicAdd(&g_as[r0 * H + head], ss0);
                atomicAdd(&g_ad[r0 * H + head], sd0);
            }
            if (r0 + 8 < M) {
                atomicAdd(&g_as[(r0 + 8) * H + head], ss8);
                atomicAdd(&g_ad[(r0 + 8) * H + head], sd8);
            }
        }
    }
}

// ============== single-pass softmax + gather-aggregate (warp per node) =============
// h gathered as fp16 (half the bytes), accumulated in fp32.
// MODE 0: fp32 out (+bias). MODE 1: bias+ELU then split-write bf16 hi/lo to g_ahi/g_alo.
template <int H, int C, int MODE>
__global__ __launch_bounds__(256) void agg_kernel(const float* __restrict__ bias,
                                                  float* __restrict__ out, int n) {
    const int F = H * C, VC = F / 32, G = C / VC, NH2 = VC / 2;
    int gid = blockIdx.x * blockDim.x + threadIdx.x;
    int node = gid >> 5, lane = gid & 31;
    if (node >= n) return;
    int start = g_rowptr[node], end = g_rowptr[node + 1];
    int myh = lane / G;
    float adh = g_ad[node * H + myh];

    float den = 0.f;
    float acc[VC];
#pragma unroll
    for (int i = 0; i < VC; i++) acc[i] = 0.f;
    const __half2* HB = (const __half2*)g_h;
    int lofs = lane * NH2;

    int e = start;
    for (; e + 3 < end; e += 4) {  // 4-edge unroll for MLP
        int s0 = g_esrc[e], s1 = g_esrc[e + 1], s2 = g_esrc[e + 2], s3 = g_esrc[e + 3];
        __half2 t0[NH2], t1[NH2], t2[NH2], t3[NH2];
        const __half2* p0 = HB + (size_t)s0 * (F / 2) + lofs;
        const __half2* p1 = HB + (size_t)s1 * (F / 2) + lofs;
        const __half2* p2 = HB + (size_t)s2 * (F / 2) + lofs;
        const __half2* p3 = HB + (size_t)s3 * (F / 2) + lofs;
#pragma unroll
        for (int i = 0; i < NH2; i++) {
            t0[i] = p0[i];
            t1[i] = p1[i];
            t2[i] = p2[i];
            t3[i] = p3[i];
        }
        float v0 = g_as[s0 * H + myh] + adh;
        float v1 = g_as[s1 * H + myh] + adh;
        float v2 = g_as[s2 * H + myh] + adh;
        float v3 = g_as[s3 * H + myh] + adh;
        v0 = v0 > 0.f ? v0 : 0.2f * v0;
        v1 = v1 > 0.f ? v1 : 0.2f * v1;
        v2 = v2 > 0.f ? v2 : 0.2f * v2;
        v3 = v3 > 0.f ? v3 : 0.2f * v3;
        float w0 = __expf(v0), w1 = __expf(v1), w2 = __expf(v2), w3 = __expf(v3);
        den += (w0 + w1) + (w2 + w3);
#pragma unroll
        for (int i = 0; i < NH2; i++) {
            float2 f0 = __half22float2(t0[i]), f1 = __half22float2(t1[i]);
            float2 f2 = __half22float2(t2[i]), f3 = __half22float2(t3[i]);
            acc[2 * i] += w0 * f0.x + w1 * f1.x + w2 * f2.x + w3 * f3.x;
            acc[2 * i + 1] += w0 * f0.y + w1 * f1.y + w2 * f2.y + w3 * f3.y;
        }
    }
    for (; e < end; e++) {
        int s = g_esrc[e];
        float v = g_as[s * H + myh] + adh;
        v = v > 0.f ? v : 0.2f * v;
        float w = __expf(v);
        den += w;
        const __half2* hp = HB + (size_t)s * (F / 2) + lofs;
#pragma unroll
        for (int i = 0; i < NH2; i++) {
            float2 f = __half22float2(hp[i]);
            acc[2 * i] += w * f.x;
            acc[2 * i + 1] += w * f.y;
        }
    }
    float inv = 1.f / (den + 1e-16f);

    const float* bp = bias + lane * VC;
#pragma unroll
    for (int i = 0; i < VC; i++) {
        float r = acc[i] * inv + bp[i];
        if (MODE == 0) {
            out[(size_t)node * F + lane * VC + i] = r;
        } else {
            r = r > 0.f ? r : __expf(r) - 1.f;
            __nv_bfloat16 hi = __float2bfloat16(r);
            size_t ch = (size_t)node * F + lane * VC + i;
            g_ahi[ch] = hi;
            g_alo[ch] = __float2bfloat16(r - __bfloat162float(hi));
        }
    }
}

// =================================== host side =====================================
extern "C" void kernel_launch(void* const* d_in, const int* in_sizes, int n_in,
                              void* d_out, int out_size) {
    const float* x = (const float*)d_in[0];
    const void* eidx = d_in[1];
    const float* W1 = (const float*)d_in[2];
    const float* as1 = (const float*)d_in[3];
    const float* ad1 = (const float*)d_in[4];
    const float* b1 = (const float*)d_in[5];
    const float* W2 = (const float*)d_in[6];
    const float* as2 = (const float*)d_in[7];
    const float* ad2 = (const float*)d_in[8];
    const float* b2 = (const float*)d_in[9];
    const float* W3 = (const float*)d_in[10];
    const float* as3 = (const float*)d_in[11];
    const float* ad3 = (const float*)d_in[12];
    const float* b3 = (const float*)d_in[13];

    int n = in_sizes[0] / 256;
    int E = in_sizes[1] / 2;
    int ET = E + n;

    __half* hbuf = nullptr;
    cudaGetSymbolAddress((void**)&hbuf, g_h);

    cudaFuncSetAttribute(hmma_gemm_kernel, cudaFuncAttributeMaxDynamicSharedMemorySize,
                         NSTG * STG_B);

    int nb = (n + 1023) / 1024;

    // ---- CSR build (graph identical across layers) ----
    detect_kernel<<<1, 1024>>>((const unsigned int*)eidx, E);
    zero_cnt_kernel<<<(n + 255) / 256, 256>>>(n);
    decode_count_kernel<<<(ET + 255) / 256, 256>>>(eidx, E, n);
    scan1_kernel<<<nb, 1024>>>(n);
    scan2_kernel<<<1, 1>>>(nb);
    scan3_kernel<<<(n + 255) / 256, 256>>>(n);
    cursor_kernel<<<(n + 255) / 256, 256>>>(n);
    scatter_kernel<<<(ET + 255) / 256, 256>>>(ET);

    int warp_blocks = (n * 32 + 255) / 256;
    int cnt4 = n * 64;
    int cblk = (cnt4 + 255) / 256;
    int mtiles = (n + 127) / 128;
    int zs4 = (n * 4 + 255) / 256;
    int zs1 = (n + 255) / 256;

    // ---- layer 1: 256 -> 4x64, elu ----
    asplit_kernel<<<cblk, 256>>>(x, cnt4);
    wsplit_kernel<<<(256 * 256 + 255) / 256, 256>>>(W1, 256, 256 * 256);
    zero_scores_kernel<<<zs4, 256>>>(n * 4);
    hmma_gemm_kernel<<<dim3(mtiles, 4), 256, NSTG * STG_B>>>(hbuf, n, 256, as1, ad1, 64, 4);
    agg_kernel<4, 64, 1><<<warp_blocks, 256>>>(b1, nullptr, n);  // writes g_ahi/g_alo

    // ---- layer 2: 256 -> 4x64, elu ----
    wsplit_kernel<<<(256 * 256 + 255) / 256, 256>>>(W2, 256, 256 * 256);
    zero_scores_kernel<<<zs4, 256>>>(n * 4);
    hmma_gemm_kernel<<<dim3(mtiles, 4), 256, NSTG * STG_B>>>(hbuf, n, 256, as2, ad2, 64, 4);
    agg_kernel<4, 64, 1><<<warp_blocks, 256>>>(b2, nullptr, n);  // writes g_ahi/g_alo

    // ---- layer 3: 256 -> 1x128, no activation, write d_out ----
    wsplit_kernel<<<(256 * 128 + 255) / 256, 256>>>(W3, 128, 256 * 128);
    zero_scores_kernel<<<zs1, 256>>>(n);
    hmma_gemm_kernel<<<dim3(mtiles, 2), 256, NSTG * STG_B>>>(hbuf, n, 128, as3, ad3, 128, 1);
    agg_kernel<1, 128, 0><<<warp_blocks, 256>>>(b3, (float*)d_out, n);
}

// round 13
// speedup vs baseline: 1.2531x; 1.2531x over previous
#include <cuda_runtime.h>
#include <cuda_bf16.h>
#include <cuda_fp16.h>
#include <cstdint>
#include <cstddef>

// ---------------- problem constants ----------------
#define NMAX 50000
#define EMAX 800000
#define ETMAX (EMAX + NMAX)

// ---------------- device scratch ----------------
__device__ int   g_is64;
__device__ int   g_src[ETMAX];
__device__ int   g_dst[ETMAX];
__device__ int   g_cnt[NMAX];
__device__ int   g_rowptr[NMAX + 1];
__device__ int   g_cursor[NMAX];
__device__ int   g_part[64];
__device__ int   g_esrc[ETMAX];
__device__ __half g_h[(size_t)NMAX * 256];   // GEMM output, fp16 (agg gather only)
__device__ float g_as[(size_t)NMAX * 4];     // per-node src scores [N,H]
__device__ float g_ad[(size_t)NMAX * 4];     // per-node dst scores [N,H]
__device__ __nv_bfloat16 g_ahi[(size_t)NMAX * 256];  // A split hi (next GEMM input)
__device__ __nv_bfloat16 g_alo[(size_t)NMAX * 256];  // A split lo
__device__ __nv_bfloat16 g_bhi[256 * 256];           // W^T split hi [N,K]
__device__ __nv_bfloat16 g_blo[256 * 256];           // W^T split lo [N,K]

// =============================== CSR construction ==================================
__global__ void detect_kernel(const unsigned int* __restrict__ p, int E) {
    __shared__ int sor;
    if (threadIdx.x == 0) sor = 0;
    __syncthreads();
    int ns = E < 2048 ? E : 2048;
    unsigned int acc = 0;
    for (int i = threadIdx.x; i < ns; i += blockDim.x) acc |= p[2 * i + 1];
    if (acc) atomicOr(&sor, 1);
    __syncthreads();
    if (threadIdx.x == 0) g_is64 = (sor == 0) ? 1 : 0;
}
__global__ void zero_cnt_kernel(int n) {
    int i = blockIdx.x * blockDim.x + threadIdx.x;
    if (i < n) g_cnt[i] = 0;
}
__global__ void decode_count_kernel(const void* __restrict__ eptr, int E, int n) {
    int i = blockIdx.x * blockDim.x + threadIdx.x;
    int ET = E + n;
    if (i >= ET) return;
    int s, d;
    if (i >= E) {
        s = d = i - E;
    } else if (g_is64) {
        const long long* p = (const long long*)eptr;
        s = (int)p[i];
        d = (int)p[(size_t)E + i];
    } else {
        const int* p = (const int*)eptr;
        s = p[i];
        d = p[E + i];
    }
    g_src[i] = s;
    g_dst[i] = d;
    atomicAdd(&g_cnt[d], 1);
}
__global__ void scan1_kernel(int n) {
    __shared__ int sh[1024];
    int i = blockIdx.x * 1024 + threadIdx.x;
    int v = (i < n) ? g_cnt[i] : 0;
    sh[threadIdx.x] = v;
    __syncthreads();
    for (int o = 1; o < 1024; o <<= 1) {
        int t = (threadIdx.x >= o) ? sh[threadIdx.x - o] : 0;
        __syncthreads();
        sh[threadIdx.x] += t;
        __syncthreads();
    }
    if (i < n) g_rowptr[i + 1] = sh[threadIdx.x];
    if (threadIdx.x == 1023) g_part[blockIdx.x] = sh[1023];
}
__global__ void scan2_kernel(int nb) {
    int acc = 0;
    for (int i = 0; i < nb; i++) {
        int t = g_part[i];
        g_part[i] = acc;
        acc += t;
    }
}
__global__ void scan3_kernel(int n) {
    int i = blockIdx.x * blockDim.x + threadIdx.x;
    if (i < n) g_rowptr[i + 1] += g_part[i >> 10];
    if (i == 0) g_rowptr[0] = 0;
}
__global__ void cursor_kernel(int n) {
    int i = blockIdx.x * blockDim.x + threadIdx.x;
    if (i < n) g_cursor[i] = g_rowptr[i];
}
__global__ void scatter_kernel(int ET) {
    int i = blockIdx.x * blockDim.x + threadIdx.x;
    if (i >= ET) return;
    int d = g_dst[i];
    int pos = atomicAdd(&g_cursor[d], 1);
    g_esrc[pos] = g_src[i];
}

// ============================ split conversions ==================================
__global__ void asplit_kernel(const float* __restrict__ src, int count4) {
    int i = blockIdx.x * blockDim.x + threadIdx.x;
    if (i >= count4) return;
    float4 v = ((const float4*)src)[i];
    __nv_bfloat16 h0 = __float2bfloat16(v.x), h1 = __float2bfloat16(v.y);
    __nv_bfloat16 h2 = __float2bfloat16(v.z), h3 = __float2bfloat16(v.w);
    __nv_bfloat16 l0 = __float2bfloat16(v.x - __bfloat162float(h0));
    __nv_bfloat16 l1 = __float2bfloat16(v.y - __bfloat162float(h1));
    __nv_bfloat16 l2 = __float2bfloat16(v.z - __bfloat162float(h2));
    __nv_bfloat16 l3 = __float2bfloat16(v.w - __bfloat162float(h3));
    __nv_bfloat162* hp = (__nv_bfloat162*)g_ahi;
    __nv_bfloat162* lp = (__nv_bfloat162*)g_alo;
    hp[2 * i] = __nv_bfloat162(h0, h1);
    hp[2 * i + 1] = __nv_bfloat162(h2, h3);
    lp[2 * i] = __nv_bfloat162(l0, l1);
    lp[2 * i + 1] = __nv_bfloat162(l2, l3);
}
// W [K=256, N] fp32 -> W^T [N, 256] (hi, lo) bf16
__global__ void wsplit_kernel(const float* __restrict__ W, int N, int total) {
    int t = blockIdx.x * blockDim.x + threadIdx.x;
    if (t >= total) return;
    int k = t & 255, n = t >> 8;
    float v = W[(size_t)k * N + n];
    __nv_bfloat16 h = __float2bfloat16(v);
    g_bhi[n * 256 + k] = h;
    g_blo[n * 256 + k] = __float2bfloat16(v - __bfloat162float(h));
}
// zero the score accumulators (GEMM epilogue atomically accumulates into them)
__global__ void zero_scores_kernel(int cnt) {
    int i = blockIdx.x * blockDim.x + threadIdx.x;
    if (i < cnt) {
        g_as[i] = 0.f;
        g_ad[i] = 0.f;
    }
}

// ========== HMMA split-3 bf16 GEMM: 3-stage cp.async + ldmatrix fragments ==========
// h[M, ldC] cols [n0, n0+64) = A[M,256] @ W[256, ldC], stored fp16 (agg-only consumer).
// Block 128x64, 8 warps (4x2), warp tile 32x32, BK=32. D = AhBh + AhBl + AlBh (fp32).
// Epilogue fuses attention-score partials (from fp32 acc) into g_as/g_ad via atomics.
#define MMA_BF16(d, a, b)                                                              \
    asm volatile(                                                                       \
        "mma.sync.aligned.m16n8k16.row.col.f32.bf16.bf16.f32 "                          \
        "{%0,%1,%2,%3}, {%4,%5,%6,%7}, {%8,%9}, {%0,%1,%2,%3};"                         \
        : "+f"((d)[0]), "+f"((d)[1]), "+f"((d)[2]), "+f"((d)[3])                        \
        : "r"((a)[0]), "r"((a)[1]), "r"((a)[2]), "r"((a)[3]), "r"((b)[0]), "r"((b)[1]))

#define LDSM_X4(r, addr)                                                               \
    asm volatile("ldmatrix.sync.aligned.m8n8.x4.shared.b16 {%0,%1,%2,%3}, [%4];"       \
                 : "=r"((r)[0]), "=r"((r)[1]), "=r"((r)[2]), "=r"((r)[3])              \
                 : "r"(addr))

__device__ __forceinline__ void cp16(uint32_t dst, const void* src, int sz) {
    asm volatile("cp.async.cg.shared.global [%0], [%1], 16, %2;" :: "r"(dst), "l"(src),
                 "r"(sz) : "memory");
}

// stage layout (bytes): Ah 0 (10240), Al 10240, Bh 20480 (5120), Bl 25600; stage=30720
#define STG_B 30720
#define NSTG 3

__global__ __launch_bounds__(256) void hmma_gemm_kernel(__half* __restrict__ C, int M, int ldC,
                                                        const float* __restrict__ a_s,
                                                        const float* __restrict__ a_d,
                                                        int Cc, int H) {
    extern __shared__ char sm[];
    int tid = threadIdx.x, wid = tid >> 5, lane = tid & 31;
    int warp_m = wid & 3, warp_n = wid >> 2;
    int g = lane >> 2, t = lane & 3;
    int m0 = blockIdx.x * 128, n0 = blockIdx.y * 64;
    uint32_t sbase = (uint32_t)__cvta_generic_to_shared(sm);

    float acc[2][4][4];
#pragma unroll
    for (int mt = 0; mt < 2; mt++)
#pragma unroll
        for (int nt = 0; nt < 4; nt++)
#pragma unroll
            for (int r = 0; r < 4; r++) acc[mt][nt][r] = 0.f;

    int arow0 = tid >> 2, aq = tid & 3;
    int brow = tid >> 2, bq = tid & 3;

    auto load_chunk = [&](int c, int stg) {
        int kc = c * 32;
        uint32_t base = sbase + stg * STG_B;
#pragma unroll
        for (int half = 0; half < 2; half++) {
            int row = arow0 + half * 64;
            int gr = m0 + row;
            int sz = (gr < M) ? 16 : 0;
            int grc = (gr < M) ? gr : 0;
            size_t go = (size_t)grc * 256 + kc + aq * 8;
            uint32_t so = base + (uint32_t)(row * 40 + aq * 8) * 2;
            cp16(so, g_ahi + go, sz);
            cp16(so + 10240, g_alo + go, sz);
        }
        {
            size_t go = (size_t)(n0 + brow) * 256 + kc + bq * 8;
            uint32_t so = base + 20480 + (uint32_t)(brow * 40 + bq * 8) * 2;
            cp16(so, g_bhi + go, 16);
            cp16(so + 5120, g_blo + go, 16);
        }
        asm volatile("cp.async.commit_group;" ::: "memory");
    };

    uint32_t aoff[2];
#pragma unroll
    for (int mt = 0; mt < 2; mt++) {
        int row = warp_m * 32 + mt * 16 + (lane & 15);
        aoff[mt] = (uint32_t)(row * 40 + ((lane >> 4) & 1) * 8) * 2;
    }
    uint32_t boff[2];
#pragma unroll
    for (int ntp = 0; ntp < 2; ntp++) {
        int row = warp_n * 32 + ntp * 16 + ((lane >> 4) & 1) * 8 + (lane & 7);
        boff[ntp] = 20480u + (uint32_t)(row * 40 + ((lane >> 3) & 1) * 8) * 2;
    }

    load_chunk(0, 0);
    load_chunk(1, 1);

    for (int c = 0; c < 8; c++) {
        int stg = c % NSTG;
        if (c < 7)
            asm volatile("cp.async.wait_group 1;" ::: "memory");
        else
            asm volatile("cp.async.wait_group 0;" ::: "memory");
        __syncthreads();
        if (c + 2 < 8) load_chunk(c + 2, (c + 2) % NSTG);

        uint32_t stbase = sbase + stg * STG_B;
#pragma unroll
        for (int kk = 0; kk < 32; kk += 16) {
            uint32_t ah[2][4], al[2][4], bh[4][2], bl[4][2];
#pragma unroll
            for (int mt = 0; mt < 2; mt++) {
                uint32_t ad = stbase + aoff[mt] + kk * 2;
                LDSM_X4(ah[mt], ad);
                LDSM_X4(al[mt], ad + 10240);
            }
#pragma unroll
            for (int ntp = 0; ntp < 2; ntp++) {
                uint32_t bd = stbase + boff[ntp] + kk * 2;
                uint32_t rh[4], rl[4];
                LDSM_X4(rh, bd);
                LDSM_X4(rl, bd + 5120);
                bh[2 * ntp][0] = rh[0];
                bh[2 * ntp][1] = rh[1];
                bh[2 * ntp + 1][0] = rh[2];
                bh[2 * ntp + 1][1] = rh[3];
                bl[2 * ntp][0] = rl[0];
                bl[2 * ntp][1] = rl[1];
                bl[2 * ntp + 1][0] = rl[2];
                bl[2 * ntp + 1][1] = rl[3];
            }
#pragma unroll
            for (int mt = 0; mt < 2; mt++)
#pragma unroll
                for (int nt = 0; nt < 4; nt++) {
                    MMA_BF16(acc[mt][nt], ah[mt], bh[nt]);
                    MMA_BF16(acc[mt][nt], ah[mt], bl[nt]);
                    MMA_BF16(acc[mt][nt], al[mt], bh[nt]);
                }
        }
    }

    // epilogue: store h (fp16) + fused score partials (fp32 acc)
    int head = n0 / Cc;
#pragma unroll
    for (int mt = 0; mt < 2; mt++) {
        int r0 = m0 + warp_m * 32 + mt * 16 + g;
        float ss0 = 0.f, sd0 = 0.f, ss8 = 0.f, sd8 = 0.f;
#pragma unroll
        for (int nt = 0; nt < 4; nt++) {
            int col = n0 + warp_n * 32 + nt * 8 + t * 2;
            if (r0 < M)
                *(__half2*)(C + (size_t)r0 * ldC + col) =
                    __floats2half2_rn(acc[mt][nt][0], acc[mt][nt][1]);
            if (r0 + 8 < M)
                *(__half2*)(C + (size_t)(r0 + 8) * ldC + col) =
                    __floats2half2_rn(acc[mt][nt][2], acc[mt][nt][3]);
            float a0 = a_s[col], a1 = a_s[col + 1];
            float d0 = a_d[col], d1 = a_d[col + 1];
            ss0 += acc[mt][nt][0] * a0 + acc[mt][nt][1] * a1;
            sd0 += acc[mt][nt][0] * d0 + acc[mt][nt][1] * d1;
            ss8 += acc[mt][nt][2] * a0 + acc[mt][nt][3] * a1;
            sd8 += acc[mt][nt][2] * d0 + acc[mt][nt][3] * d1;
        }
#pragma unroll
        for (int o = 1; o < 4; o <<= 1) {
            ss0 += __shfl_xor_sync(0xffffffffu, ss0, o);
            sd0 += __shfl_xor_sync(0xffffffffu, sd0, o);
            ss8 += __shfl_xor_sync(0xffffffffu, ss8, o);
            sd8 += __shfl_xor_sync(0xffffffffu, sd8, o);
        }
        if (t == 0) {
            if (r0 < M) {
                atomicAdd(&g_as[r0 * H + head], ss0);
                atomicAdd(&g_ad[r0 * H + head], sd0);
            }
            if (r0 + 8 < M) {
                atomicAdd(&g_as[(r0 + 8) * H + head], ss8);
                atomicAdd(&g_ad[(r0 + 8) * H + head], sd8);
            }
        }
    }
}

// ============== single-pass softmax + gather-aggregate (warp per node) =============
// h gathered as fp16 with CONTIGUOUS lane layout: lane reads one 16B (F=256) or
// 8B (F=128) vector per edge -> warp covers the row exactly (perfect sectors).
// MODE 0: fp32 out (+bias). MODE 1: bias+ELU then split-write bf16 hi/lo (vectorized).
template <int VC> struct HVec;
template <> struct HVec<8> { typedef uint4 T; };
template <> struct HVec<4> { typedef uint2 T; };

template <int H, int C, int MODE>
__global__ __launch_bounds__(256) void agg_kernel(const float* __restrict__ bias,
                                                  float* __restrict__ out, int n) {
    const int F = H * C, VC = F / 32, G = C / VC, NH2 = VC / 2;
    typedef typename HVec<VC>::T VecT;
    int gid = blockIdx.x * blockDim.x + threadIdx.x;
    int node = gid >> 5, lane = gid & 31;
    if (node >= n) return;
    int start = g_rowptr[node], end = g_rowptr[node + 1];
    int myh = lane / G;
    float adh = g_ad[node * H + myh];

    float den = 0.f;
    float acc[VC];
#pragma unroll
    for (int i = 0; i < VC; i++) acc[i] = 0.f;
    const VecT* HB = (const VecT*)g_h;  // one VecT per lane per row: index s*32 + lane

    int e = start;
    for (; e + 3 < end; e += 4) {  // 4-edge unroll for MLP
        int s0 = g_esrc[e], s1 = g_esrc[e + 1], s2 = g_esrc[e + 2], s3 = g_esrc[e + 3];
        VecT u0 = HB[(size_t)s0 * 32 + lane];
        VecT u1 = HB[(size_t)s1 * 32 + lane];
        VecT u2 = HB[(size_t)s2 * 32 + lane];
        VecT u3 = HB[(size_t)s3 * 32 + lane];
        float v0 = g_as[s0 * H + myh] + adh;
        float v1 = g_as[s1 * H + myh] + adh;
        float v2 = g_as[s2 * H + myh] + adh;
        float v3 = g_as[s3 * H + myh] + adh;
        v0 = v0 > 0.f ? v0 : 0.2f * v0;
        v1 = v1 > 0.f ? v1 : 0.2f * v1;
        v2 = v2 > 0.f ? v2 : 0.2f * v2;
        v3 = v3 > 0.f ? v3 : 0.2f * v3;
        float w0 = __expf(v0), w1 = __expf(v1), w2 = __expf(v2), w3 = __expf(v3);
        den += (w0 + w1) + (w2 + w3);
        const uint32_t* q0 = (const uint32_t*)&u0;
        const uint32_t* q1 = (const uint32_t*)&u1;
        const uint32_t* q2 = (const uint32_t*)&u2;
        const uint32_t* q3 = (const uint32_t*)&u3;
#pragma unroll
        for (int i = 0; i < NH2; i++) {
            float2 f0 = __half22float2(*(const __half2*)&q0[i]);
            float2 f1 = __half22float2(*(const __half2*)&q1[i]);
            float2 f2 = __half22float2(*(const __half2*)&q2[i]);
            float2 f3 = __half22float2(*(const __half2*)&q3[i]);
            acc[2 * i] += w0 * f0.x + w1 * f1.x + w2 * f2.x + w3 * f3.x;
            acc[2 * i + 1] += w0 * f0.y + w1 * f1.y + w2 * f2.y + w3 * f3.y;
        }
    }
    for (; e < end; e++) {
        int s = g_esrc[e];
        float v = g_as[s * H + myh] + adh;
        v = v > 0.f ? v : 0.2f * v;
        float w = __expf(v);
        den += w;
        VecT u = HB[(size_t)s * 32 + lane];
        const uint32_t* q = (const uint32_t*)&u;
#pragma unroll
        for (int i = 0; i < NH2; i++) {
            float2 f = __half22float2(*(const __half2*)&q[i]);
            acc[2 * i] += w * f.x;
            acc[2 * i + 1] += w * f.y;
        }
    }
    float inv = 1.f / (den + 1e-16f);

    const float* bp = bias + lane * VC;
    float r[VC];
#pragma unroll
    for (int i = 0; i < VC; i++) r[i] = acc[i] * inv + bp[i];

    if (MODE == 0) {
        float* op = out + (size_t)node * F + lane * VC;
#pragma unroll
        for (int i = 0; i < VC; i += 4)
            *(float4*)(op + i) = make_float4(r[i], r[i + 1], r[i + 2], r[i + 3]);
    } else {
        uint32_t hh[NH2], ll[NH2];
#pragma unroll
        for (int i = 0; i < VC; i++) r[i] = r[i] > 0.f ? r[i] : __expf(r[i]) - 1.f;
#pragma unroll
        for (int i = 0; i < NH2; i++) {
            __nv_bfloat16 h0 = __float2bfloat16(r[2 * i]);
            __nv_bfloat16 h1 = __float2bfloat16(r[2 * i + 1]);
            __nv_bfloat16 l0 = __float2bfloat16(r[2 * i] - __bfloat162float(h0));
            __nv_bfloat16 l1 = __float2bfloat16(r[2 * i + 1] - __bfloat162float(h1));
            __nv_bfloat162 hp(h0, h1), lp(l0, l1);
            hh[i] = *(const uint32_t*)&hp;
            ll[i] = *(const uint32_t*)&lp;
        }
        size_t ch = (size_t)node * F + lane * VC;
#pragma unroll
        for (int i = 0; i < NH2; i += 4) {
            *(uint4*)(g_ahi + ch + 2 * i * 4 / 4 * 4) =
                make_uint4(hh[i], hh[i + 1], hh[i + 2], hh[i + 3]);
            *(uint4*)(g_alo + ch + 2 * i * 4 / 4 * 4) =
                make_uint4(ll[i], ll[i + 1], ll[i + 2], ll[i + 3]);
        }
    }
}

// =================================== host side =====================================
extern "C" void kernel_launch(void* const* d_in, const int* in_sizes, int n_in,
                              void* d_out, int out_size) {
    const float* x = (const float*)d_in[0];
    const void* eidx = d_in[1];
    const float* W1 = (const float*)d_in[2];
    const float* as1 = (const float*)d_in[3];
    const float* ad1 = (const float*)d_in[4];
    const float* b1 = (const float*)d_in[5];
    const float* W2 = (const float*)d_in[6];
    const float* as2 = (const float*)d_in[7];
    const float* ad2 = (const float*)d_in[8];
    const float* b2 = (const float*)d_in[9];
    const float* W3 = (const float*)d_in[10];
    const float* as3 = (const float*)d_in[11];
    const float* ad3 = (const float*)d_in[12];
    const float* b3 = (const float*)d_in[13];

    int n = in_sizes[0] / 256;
    int E = in_sizes[1] / 2;
    int ET = E + n;

    __half* hbuf = nullptr;
    cudaGetSymbolAddress((void**)&hbuf, g_h);

    cudaFuncSetAttribute(hmma_gemm_kernel, cudaFuncAttributeMaxDynamicSharedMemorySize,
                         NSTG * STG_B);

    int nb = (n + 1023) / 1024;

    // ---- CSR build (graph identical across layers) ----
    detect_kernel<<<1, 1024>>>((const unsigned int*)eidx, E);
    zero_cnt_kernel<<<(n + 255) / 256, 256>>>(n);
    decode_count_kernel<<<(ET + 255) / 256, 256>>>(eidx, E, n);
    scan1_kernel<<<nb, 1024>>>(n);
    scan2_kernel<<<1, 1>>>(nb);
    scan3_kernel<<<(n + 255) / 256, 256>>>(n);
    cursor_kernel<<<(n + 255) / 256, 256>>>(n);
    scatter_kernel<<<(ET + 255) / 256, 256>>>(ET);

    int warp_blocks = (n * 32 + 255) / 256;
    int cnt4 = n * 64;
    int cblk = (cnt4 + 255) / 256;
    int mtiles = (n + 127) / 128;
    int zs4 = (n * 4 + 255) / 256;
    int zs1 = (n + 255) / 256;

    // ---- layer 1: 256 -> 4x64, elu ----
    asplit_kernel<<<cblk, 256>>>(x, cnt4);
    wsplit_kernel<<<(256 * 256 + 255) / 256, 256>>>(W1, 256, 256 * 256);
    zero_scores_kernel<<<zs4, 256>>>(n * 4);
    hmma_gemm_kernel<<<dim3(mtiles, 4), 256, NSTG * STG_B>>>(hbuf, n, 256, as1, ad1, 64, 4);
    agg_kernel<4, 64, 1><<<warp_blocks, 256>>>(b1, nullptr, n);  // writes g_ahi/g_alo

    // ---- layer 2: 256 -> 4x64, elu ----
    wsplit_kernel<<<(256 * 256 + 255) / 256, 256>>>(W2, 256, 256 * 256);
    zero_scores_kernel<<<zs4, 256>>>(n * 4);
    hmma_gemm_kernel<<<dim3(mtiles, 4), 256, NSTG * STG_B>>>(hbuf, n, 256, as2, ad2, 64, 4);
    agg_kernel<4, 64, 1><<<warp_blocks, 256>>>(b2, nullptr, n);  // writes g_ahi/g_alo

    // ---- layer 3: 256 -> 1x128, no activation, write d_out ----
    wsplit_kernel<<<(256 * 128 + 255) / 256, 256>>>(W3, 128, 256 * 128);
    zero_scores_kernel<<<zs1, 256>>>(n);
    hmma_gemm_kernel<<<dim3(mtiles, 2), 256, NSTG * STG_B>>>(hbuf, n, 128, as3, ad3, 128, 1);
    agg_kernel<1, 128, 0><<<warp_blocks, 256>>>(b3, (float*)d_out, n);
}

// round 15
// speedup vs baseline: 1.2558x; 1.0022x over previous
#include <cuda_runtime.h>
#include <cuda_bf16.h>
#include <cuda_fp16.h>
#include <cstdint>
#include <cstddef>

// ---------------- problem constants ----------------
#define NMAX 50000
#define EMAX 800000
#define ETMAX (EMAX + NMAX)

// ---------------- device scratch ----------------
__device__ int   g_is64;
__device__ int   g_src[ETMAX];
__device__ int   g_dst[ETMAX];
__device__ int   g_cnt[NMAX];
__device__ int   g_rowptr[NMAX + 1];
__device__ int   g_cursor[NMAX];
__device__ int   g_part[64];
__device__ int   g_esrc[ETMAX];
__device__ __half g_h[(size_t)NMAX * 256];   // GEMM output, fp16 (agg gather only)
__device__ float g_as[(size_t)NMAX * 4];     // per-node src scores [N,H]
__device__ float g_ad[(size_t)NMAX * 4];     // per-node dst scores [N,H]
__device__ __nv_bfloat16 g_ahi[(size_t)NMAX * 256];  // A split hi (next GEMM input)
__device__ __nv_bfloat16 g_alo[(size_t)NMAX * 256];  // A split lo
__device__ __nv_bfloat16 g_bhi[256 * 256];           // W^T split hi [N,K]
__device__ __nv_bfloat16 g_blo[256 * 256];           // W^T split lo [N,K]

// =============================== CSR construction ==================================
// zero_cnt fused with int64 detection (block 0 does the detect scan)
__global__ void init_detect_kernel(const unsigned int* __restrict__ p, int E, int n) {
    int i = blockIdx.x * blockDim.x + threadIdx.x;
    if (i < n) g_cnt[i] = 0;
    if (blockIdx.x == 0) {
        __shared__ int sor;
        if (threadIdx.x == 0) sor = 0;
        __syncthreads();
        int ns = E < 2048 ? E : 2048;
        unsigned int acc = 0;
        for (int j = threadIdx.x; j < ns; j += blockDim.x) acc |= p[2 * j + 1];
        if (acc) atomicOr(&sor, 1);
        __syncthreads();
        if (threadIdx.x == 0) g_is64 = (sor == 0) ? 1 : 0;
    }
}
__global__ void decode_count_kernel(const void* __restrict__ eptr, int E, int n) {
    int i = blockIdx.x * blockDim.x + threadIdx.x;
    int ET = E + n;
    if (i >= ET) return;
    int s, d;
    if (i >= E) {
        s = d = i - E;
    } else if (g_is64) {
        const long long* p = (const long long*)eptr;
        s = (int)p[i];
        d = (int)p[(size_t)E + i];
    } else {
        const int* p = (const int*)eptr;
        s = p[i];
        d = p[E + i];
    }
    g_src[i] = s;
    g_dst[i] = d;
    atomicAdd(&g_cnt[d], 1);
}
__global__ void scan1_kernel(int n) {
    __shared__ int sh[1024];
    int i = blockIdx.x * 1024 + threadIdx.x;
    int v = (i < n) ? g_cnt[i] : 0;
    sh[threadIdx.x] = v;
    __syncthreads();
    for (int o = 1; o < 1024; o <<= 1) {
        int t = (threadIdx.x >= o) ? sh[threadIdx.x - o] : 0;
        __syncthreads();
        sh[threadIdx.x] += t;
        __syncthreads();
    }
    if (i < n) g_rowptr[i + 1] = sh[threadIdx.x];
    if (threadIdx.x == 1023) g_part[blockIdx.x] = sh[1023];
}
// parallel exclusive scan over <=64 block sums (was a 1-thread latency chain)
__global__ void scan2_kernel(int nb) {
    int i = threadIdx.x;  // blockDim = 64
    int lane = i & 31, w = i >> 5;
    int v = (i < nb) ? g_part[i] : 0;
    int x = v;
#pragma unroll
    for (int o = 1; o < 32; o <<= 1) {
        int t = __shfl_up_sync(0xffffffffu, x, o);
        if (lane >= o) x += t;
    }
    __shared__ int wsum;
    if (w == 0 && lane == 31) wsum = x;
    __syncthreads();
    if (w == 1) x += wsum;
    if (i < nb) g_part[i] = x - v;  // exclusive
}
// add block offsets + emit cursor (cursor[i+1] computed locally -> no race)
__global__ void scan3_kernel(int n) {
    int i = blockIdx.x * blockDim.x + threadIdx.x;
    if (i < n) {
        int v = g_rowptr[i + 1] + g_part[i >> 10];
        g_rowptr[i + 1] = v;
        if (i + 1 < n) g_cursor[i + 1] = v;
    }
    if (i == 0) {
        g_rowptr[0] = 0;
        g_cursor[0] = 0;
    }
}
__global__ void scatter_kernel(int ET) {
    int i = blockIdx.x * blockDim.x + threadIdx.x;
    if (i >= ET) return;
    int d = g_dst[i];
    int pos = atomicAdd(&g_cursor[d], 1);
    g_esrc[pos] = g_src[i];
}

// ============================ split conversions ==================================
__global__ void asplit_kernel(const float* __restrict__ src, int count4) {
    int i = blockIdx.x * blockDim.x + threadIdx.x;
    if (i >= count4) return;
    float4 v = ((const float4*)src)[i];
    __nv_bfloat16 h0 = __float2bfloat16(v.x), h1 = __float2bfloat16(v.y);
    __nv_bfloat16 h2 = __float2bfloat16(v.z), h3 = __float2bfloat16(v.w);
    __nv_bfloat16 l0 = __float2bfloat16(v.x - __bfloat162float(h0));
    __nv_bfloat16 l1 = __float2bfloat16(v.y - __bfloat162float(h1));
    __nv_bfloat16 l2 = __float2bfloat16(v.z - __bfloat162float(h2));
    __nv_bfloat16 l3 = __float2bfloat16(v.w - __bfloat162float(h3));
    __nv_bfloat162* hp = (__nv_bfloat162*)g_ahi;
    __nv_bfloat162* lp = (__nv_bfloat162*)g_alo;
    hp[2 * i] = __nv_bfloat162(h0, h1);
    hp[2 * i + 1] = __nv_bfloat162(h2, h3);
    lp[2 * i] = __nv_bfloat162(l0, l1);
    lp[2 * i + 1] = __nv_bfloat162(l2, l3);
}
// W [K=256, N] fp32 -> W^T [N, 256] (hi, lo) bf16; also zeroes zcnt score slots
__global__ void wsplit_kernel(const float* __restrict__ W, int N, int total, int zcnt) {
    int t = blockIdx.x * blockDim.x + threadIdx.x;
    if (t < zcnt) {
        g_as[t] = 0.f;
        g_ad[t] = 0.f;
    }
    if (t >= total) return;
    int k = t & 255, n = t >> 8;
    float v = W[(size_t)k * N + n];
    __nv_bfloat16 h = __float2bfloat16(v);
    g_bhi[n * 256 + k] = h;
    g_blo[n * 256 + k] = __float2bfloat16(v - __bfloat162float(h));
}

// ========== HMMA split-3 bf16 GEMM: 3-stage cp.async + ldmatrix fragments ==========
// Block 128x64, 8 warps (4x2), warp tile 32x32, BK=32. D = AhBh + AhBl + AlBh (fp32).
// Scores: ATOMIC=false (Cc==64, one y-block per head) -> smem reduce + plain store;
//         ATOMIC=true  (layer 3) -> global atomicAdd (g_as/g_ad pre-zeroed).
#define MMA_BF16(d, a, b)                                                              \
    asm volatile(                                                                       \
        "mma.sync.aligned.m16n8k16.row.col.f32.bf16.bf16.f32 "                          \
        "{%0,%1,%2,%3}, {%4,%5,%6,%7}, {%8,%9}, {%0,%1,%2,%3};"                         \
        : "+f"((d)[0]), "+f"((d)[1]), "+f"((d)[2]), "+f"((d)[3])                        \
        : "r"((a)[0]), "r"((a)[1]), "r"((a)[2]), "r"((a)[3]), "r"((b)[0]), "r"((b)[1]))

#define LDSM_X4(r, addr)                                                               \
    asm volatile("ldmatrix.sync.aligned.m8n8.x4.shared.b16 {%0,%1,%2,%3}, [%4];"       \
                 : "=r"((r)[0]), "=r"((r)[1]), "=r"((r)[2]), "=r"((r)[3])              \
                 : "r"(addr))

__device__ __forceinline__ void cp16(uint32_t dst, const void* src, int sz) {
    asm volatile("cp.async.cg.shared.global [%0], [%1], 16, %2;" :: "r"(dst), "l"(src),
                 "r"(sz) : "memory");
}

// stage layout (bytes): Ah 0 (10240), Al 10240, Bh 20480 (5120), Bl 25600; stage=30720
#define STG_B 30720
#define NSTG 3

template <bool ATOMIC>
__global__ __launch_bounds__(256) void hmma_gemm_kernel(__half* __restrict__ C, int M, int ldC,
                                                        const float* __restrict__ a_s,
                                                        const float* __restrict__ a_d,
                                                        int Cc, int H) {
    extern __shared__ char sm[];
    int tid = threadIdx.x, wid = tid >> 5, lane = tid & 31;
    int warp_m = wid & 3, warp_n = wid >> 2;
    int g = lane >> 2, t = lane & 3;
    int m0 = blockIdx.x * 128, n0 = blockIdx.y * 64;
    uint32_t sbase = (uint32_t)__cvta_generic_to_shared(sm);

    float acc[2][4][4];
#pragma unroll
    for (int mt = 0; mt < 2; mt++)
#pragma unroll
        for (int nt = 0; nt < 4; nt++)
#pragma unroll
            for (int r = 0; r < 4; r++) acc[mt][nt][r] = 0.f;

    int arow0 = tid >> 2, aq = tid & 3;
    int brow = tid >> 2, bq = tid & 3;

    auto load_chunk = [&](int c, int stg) {
        int kc = c * 32;
        uint32_t base = sbase + stg * STG_B;
#pragma unroll
        for (int half = 0; half < 2; half++) {
            int row = arow0 + half * 64;
            int gr = m0 + row;
            int sz = (gr < M) ? 16 : 0;
            int grc = (gr < M) ? gr : 0;
            size_t go = (size_t)grc * 256 + kc + aq * 8;
            uint32_t so = base + (uint32_t)(row * 40 + aq * 8) * 2;
            cp16(so, g_ahi + go, sz);
            cp16(so + 10240, g_alo + go, sz);
        }
        {
            size_t go = (size_t)(n0 + brow) * 256 + kc + bq * 8;
            uint32_t so = base + 20480 + (uint32_t)(brow * 40 + bq * 8) * 2;
            cp16(so, g_bhi + go, 16);
            cp16(so + 5120, g_blo + go, 16);
        }
        asm volatile("cp.async.commit_group;" ::: "memory");
    };

    uint32_t aoff[2];
#pragma unroll
    for (int mt = 0; mt < 2; mt++) {
        int row = warp_m * 32 + mt * 16 + (lane & 15);
        aoff[mt] = (uint32_t)(row * 40 + ((lane >> 4) & 1) * 8) * 2;
    }
    uint32_t boff[2];
#pragma unroll
    for (int ntp = 0; ntp < 2; ntp++) {
        int row = warp_n * 32 + ntp * 16 + ((lane >> 4) & 1) * 8 + (lane & 7);
        boff[ntp] = 20480u + (uint32_t)(row * 40 + ((lane >> 3) & 1) * 8) * 2;
    }

    load_chunk(0, 0);
    load_chunk(1, 1);

    for (int c = 0; c < 8; c++) {
        int stg = c % NSTG;
        if (c < 7)
            asm volatile("cp.async.wait_group 1;" ::: "memory");
        else
            asm volatile("cp.async.wait_group 0;" ::: "memory");
        __syncthreads();
        if (c + 2 < 8) load_chunk(c + 2, (c + 2) % NSTG);

        uint32_t stbase = sbase + stg * STG_B;
#pragma unroll
        for (int kk = 0; kk < 32; kk += 16) {
            uint32_t ah[2][4], al[2][4], bh[4][2], bl[4][2];
#pragma unroll
            for (int mt = 0; mt < 2; mt++) {
                uint32_t ad = stbase + aoff[mt] + kk * 2;
                LDSM_X4(ah[mt], ad);
                LDSM_X4(al[mt], ad + 10240);
            }
#pragma unroll
            for (int ntp = 0; ntp < 2; ntp++) {
                uint32_t bd = stbase + boff[ntp] + kk * 2;
                uint32_t rh[4], rl[4];
                LDSM_X4(rh, bd);
                LDSM_X4(rl, bd + 5120);
                bh[2 * ntp][0] = rh[0];
                bh[2 * ntp][1] = rh[1];
                bh[2 * ntp + 1][0] = rh[2];
                bh[2 * ntp + 1][1] = rh[3];
                bl[2 * ntp][0] = rl[0];
                bl[2 * ntp][1] = rl[1];
                bl[2 * ntp + 1][0] = rl[2];
                bl[2 * ntp + 1][1] = rl[3];
            }
#pragma unroll
            for (int mt = 0; mt < 2; mt++)
#pragma unroll
                for (int nt = 0; nt < 4; nt++) {
                    MMA_BF16(acc[mt][nt], ah[mt], bh[nt]);
                    MMA_BF16(acc[mt][nt], ah[mt], bl[nt]);
                    MMA_BF16(acc[mt][nt], al[mt], bh[nt]);
                }
        }
    }

    // smem score-reduction buffers (reuse stage 0; all stage reads are done)
    float* sss = (float*)sm;
    float* ssd = (float*)(sm + 512);
    if (!ATOMIC) {
        __syncthreads();
        if (tid < 128) {
            sss[tid] = 0.f;
            ssd[tid] = 0.f;
        }
        __syncthreads();
    }

    int head = n0 / Cc;
#pragma unroll
    for (int mt = 0; mt < 2; mt++) {
        int rl0 = warp_m * 32 + mt * 16 + g;  // local row
        int r0 = m0 + rl0;
        float ss0 = 0.f, sd0 = 0.f, ss8 = 0.f, sd8 = 0.f;
#pragma unroll
        for (int nt = 0; nt < 4; nt++) {
            int col = n0 + warp_n * 32 + nt * 8 + t * 2;
            if (r0 < M)
                *(__half2*)(C + (size_t)r0 * ldC + col) =
                    __floats2half2_rn(acc[mt][nt][0], acc[mt][nt][1]);
            if (r0 + 8 < M)
                *(__half2*)(C + (size_t)(r0 + 8) * ldC + col) =
                    __floats2half2_rn(acc[mt][nt][2], acc[mt][nt][3]);
            float a0 = a_s[col], a1 = a_s[col + 1];
            float d0 = a_d[col], d1 = a_d[col + 1];
            ss0 += acc[mt][nt][0] * a0 + acc[mt][nt][1] * a1;
            sd0 += acc[mt][nt][0] * d0 + acc[mt][nt][1] * d1;
            ss8 += acc[mt][nt][2] * a0 + acc[mt][nt][3] * a1;
            sd8 += acc[mt][nt][2] * d0 + acc[mt][nt][3] * d1;
        }
#pragma unroll
        for (int o = 1; o < 4; o <<= 1) {
            ss0 += __shfl_xor_sync(0xffffffffu, ss0, o);
            sd0 += __shfl_xor_sync(0xffffffffu, sd0, o);
            ss8 += __shfl_xor_sync(0xffffffffu, ss8, o);
            sd8 += __shfl_xor_sync(0xffffffffu, sd8, o);
        }
        if (t == 0) {
            if (ATOMIC) {
                if (r0 < M) {
                    atomicAdd(&g_as[r0 * H + head], ss0);
                    atomicAdd(&g_ad[r0 * H + head], sd0);
                }
                if (r0 + 8 < M) {
                    atomicAdd(&g_as[(r0 + 8) * H + head], ss8);
                    atomicAdd(&g_ad[(r0 + 8) * H + head], sd8);
                }
            } else {
                atomicAdd(&sss[rl0], ss0);
                atomicAdd(&ssd[rl0], sd0);
                atomicAdd(&sss[rl0 + 8], ss8);
                atomicAdd(&ssd[rl0 + 8], sd8);
            }
        }
    }
    if (!ATOMIC) {
        __syncthreads();
        if (tid < 128) {
            int gr = m0 + tid;
            if (gr < M) {
                g_as[gr * H + head] = sss[tid];
                g_ad[gr * H + head] = ssd[tid];
            }
        }
    }
}

// ============== single-pass softmax + gather-aggregate (warp per node) =============
// h gathered as fp16, contiguous lane layout (one 16B/8B vector per lane per edge).
// MODE 0: fp32 out (+bias). MODE 1: bias+ELU then split-write bf16 hi/lo (vectorized).
template <int VC> struct HVec;
template <> struct HVec<8> { typedef uint4 T; };
template <> struct HVec<4> { typedef uint2 T; };

template <int H, int C, int MODE>
__global__ __launch_bounds__(256) void agg_kernel(const float* __restrict__ bias,
                                                  float* __restrict__ out, int n) {
    const int F = H * C, VC = F / 32, G = C / VC, NH2 = VC / 2;
    typedef typename HVec<VC>::T VecT;
    int gid = blockIdx.x * blockDim.x + threadIdx.x;
    int node = gid >> 5, lane = gid & 31;
    if (node >= n) return;
    int start = g_rowptr[node], end = g_rowptr[node + 1];
    int myh = lane / G;
    float adh = g_ad[node * H + myh];

    float den = 0.f;
    float acc[VC];
#pragma unroll
    for (int i = 0; i < VC; i++) acc[i] = 0.f;
    const VecT* HB = (const VecT*)g_h;

    int e = start;
    for (; e + 3 < end; e += 4) {
        int s0 = g_esrc[e], s1 = g_esrc[e + 1], s2 = g_esrc[e + 2], s3 = g_esrc[e + 3];
        VecT u0 = HB[(size_t)s0 * 32 + lane];
        VecT u1 = HB[(size_t)s1 * 32 + lane];
        VecT u2 = HB[(size_t)s2 * 32 + lane];
        VecT u3 = HB[(size_t)s3 * 32 + lane];
        float v0 = g_as[s0 * H + myh] + adh;
        float v1 = g_as[s1 * H + myh] + adh;
        float v2 = g_as[s2 * H + myh] + adh;
        float v3 = g_as[s3 * H + myh] + adh;
        v0 = v0 > 0.f ? v0 : 0.2f * v0;
        v1 = v1 > 0.f ? v1 : 0.2f * v1;
        v2 = v2 > 0.f ? v2 : 0.2f * v2;
        v3 = v3 > 0.f ? v3 : 0.2f * v3;
        float w0 = __expf(v0), w1 = __expf(v1), w2 = __expf(v2), w3 = __expf(v3);
        den += (w0 + w1) + (w2 + w3);
        const uint32_t* q0 = (const uint32_t*)&u0;
        const uint32_t* q1 = (const uint32_t*)&u1;
        const uint32_t* q2 = (const uint32_t*)&u2;
        const uint32_t* q3 = (const uint32_t*)&u3;
#pragma unroll
        for (int i = 0; i < NH2; i++) {
            float2 f0 = __half22float2(*(const __half2*)&q0[i]);
            float2 f1 = __half22float2(*(const __half2*)&q1[i]);
            float2 f2 = __half22float2(*(const __half2*)&q2[i]);
            float2 f3 = __half22float2(*(const __half2*)&q3[i]);
            acc[2 * i] += w0 * f0.x + w1 * f1.x + w2 * f2.x + w3 * f3.x;
            acc[2 * i + 1] += w0 * f0.y + w1 * f1.y + w2 * f2.y + w3 * f3.y;
        }
    }
    for (; e < end; e++) {
        int s = g_esrc[e];
        float v = g_as[s * H + myh] + adh;
        v = v > 0.f ? v : 0.2f * v;
        float w = __expf(v);
        den += w;
        VecT u = HB[(size_t)s * 32 + lane];
        const uint32_t* q = (const uint32_t*)&u;
#pragma unroll
        for (int i = 0; i < NH2; i++) {
            float2 f = __half22float2(*(const __half2*)&q[i]);
            acc[2 * i] += w * f.x;
            acc[2 * i + 1] += w * f.y;
        }
    }
    float inv = 1.f / (den + 1e-16f);

    const float* bp = bias + lane * VC;
    float r[VC];
#pragma unroll
    for (int i = 0; i < VC; i++) r[i] = acc[i] * inv + bp[i];

    if (MODE == 0) {
        float* op = out + (size_t)node * F + lane * VC;
#pragma unroll
        for (int i = 0; i < VC; i += 4)
            *(float4*)(op + i) = make_float4(r[i], r[i + 1], r[i + 2], r[i + 3]);
    } else {
        uint32_t hh[NH2], ll[NH2];
#pragma unroll
        for (int i = 0; i < VC; i++) r[i] = r[i] > 0.f ? r[i] : __expf(r[i]) - 1.f;
#pragma unroll
        for (int i = 0; i < NH2; i++) {
            __nv_bfloat16 h0 = __float2bfloat16(r[2 * i]);
            __nv_bfloat16 h1 = __float2bfloat16(r[2 * i + 1]);
            __nv_bfloat16 l0 = __float2bfloat16(r[2 * i] - __bfloat162float(h0));
            __nv_bfloat16 l1 = __float2bfloat16(r[2 * i + 1] - __bfloat162float(h1));
            __nv_bfloat162 hp(h0, h1), lp(l0, l1);
            hh[i] = *(const uint32_t*)&hp;
            ll[i] = *(const uint32_t*)&lp;
        }
        size_t ch = (size_t)node * F + lane * VC;
#pragma unroll
        for (int i = 0; i < NH2; i += 4) {
            *(uint4*)(g_ahi + ch + 2 * i) = make_uint4(hh[i], hh[i + 1], hh[i + 2], hh[i + 3]);
            *(uint4*)(g_alo + ch + 2 * i) = make_uint4(ll[i], ll[i + 1], ll[i + 2], ll[i + 3]);
        }
    }
}

// =================================== host side =====================================
extern "C" void kernel_launch(void* const* d_in, const int* in_sizes, int n_in,
                              void* d_out, int out_size) {
    const float* x = (const float*)d_in[0];
    const void* eidx = d_in[1];
    const float* W1 = (const float*)d_in[2];
    const float* as1 = (const float*)d_in[3];
    const float* ad1 = (const float*)d_in[4];
    const float* b1 = (const float*)d_in[5];
    const float* W2 = (const float*)d_in[6];
    const float* as2 = (const float*)d_in[7];
    const float* ad2 = (const float*)d_in[8];
    const float* b2 = (const float*)d_in[9];
    const float* W3 = (const float*)d_in[10];
    const float* as3 = (const float*)d_in[11];
    const float* ad3 = (const float*)d_in[12];
    const float* b3 = (const float*)d_in[13];

    int n = in_sizes[0] / 256;
    int E = in_sizes[1] / 2;
    int ET = E + n;

    __half* hbuf = nullptr;
    cudaGetSymbolAddress((void**)&hbuf, g_h);

    cudaFuncSetAttribute(hmma_gemm_kernel<false>, cudaFuncAttributeMaxDynamicSharedMemorySize,
                         NSTG * STG_B);
    cudaFuncSetAttribute(hmma_gemm_kernel<true>, cudaFuncAttributeMaxDynamicSharedMemorySize,
                         NSTG * STG_B);

    int nb = (n + 1023) / 1024;

    // ---- CSR build (graph identical across layers) ----
    init_detect_kernel<<<(n + 255) / 256, 256>>>((const unsigned int*)eidx, E, n);
    decode_count_kernel<<<(ET + 255) / 256, 256>>>(eidx, E, n);
    scan1_kernel<<<nb, 1024>>>(n);
    scan2_kernel<<<1, 64>>>(nb);
    scan3_kernel<<<(n + 255) / 256, 256>>>(n);
    scatter_kernel<<<(ET + 255) / 256, 256>>>(ET);

    int warp_blocks = (n * 32 + 255) / 256;
    int cnt4 = n * 64;
    int cblk = (cnt4 + 255) / 256;
    int mtiles = (n + 127) / 128;

    // ---- layer 1: 256 -> 4x64, elu ----
    asplit_kernel<<<cblk, 256>>>(x, cnt4);
    wsplit_kernel<<<(256 * 256 + 255) / 256, 256>>>(W1, 256, 256 * 256, 0);
    hmma_gemm_kernel<false><<<dim3(mtiles, 4), 256, NSTG * STG_B>>>(hbuf, n, 256, as1, ad1, 64, 4);
    agg_kernel<4, 64, 1><<<warp_blocks, 256>>>(b1, nullptr, n);  // writes g_ahi/g_alo

    // ---- layer 2: 256 -> 4x64, elu ----
    wsplit_kernel<<<(256 * 256 + 255) / 256, 256>>>(W2, 256, 256 * 256, 0);
    hmma_gemm_kernel<false><<<dim3(mtiles, 4), 256, NSTG * STG_B>>>(hbuf, n, 256, as2, ad2, 64, 4);
    agg_kernel<4, 64, 1><<<warp_blocks, 256>>>(b2, nullptr, n);  // writes g_ahi/g_alo

    // ---- layer 3: 256 -> 1x128, no activation, write d_out ----
    // wsplit grid covers both the 32768 W elements and the n score zeros
    {
        int tot = 256 * 128;
        int gmax = ((tot > n ? tot : n) + 255) / 256;
        wsplit_kernel<<<gmax, 256>>>(W3, 128, tot, n);
    }
    hmma_gemm_kernel<true><<<dim3(mtiles, 2), 256, NSTG * STG_B>>>(hbuf, n, 128, as3, ad3, 128, 1);
    agg_kernel<1, 128, 0><<<warp_blocks, 256>>>(b3, (float*)d_out, n);
}